// round 12
// baseline (speedup 1.0000x reference)
#include <cuda_runtime.h>
#include <cuda_fp16.h>
#include <math.h>
#include <stdint.h>

// Problem constants
constexpr int B  = 4;
constexpr int T  = 2048;
constexpr int D  = 768;
constexpr int H  = 12;
constexpr int HD = 64;
constexpr int BT = B * T;          // 8192
constexpr int NQKV = 3 * D;        // 2304
constexpr float EPS  = 1e-4f;
constexpr float GAIN = 1.8402f;

constexpr int Dh   = D / 2;        // 384 uint32 (half2) per row

// GEMM: 256x128 tile, 512 threads (16 warps = 8m x 2n), 64-half chunks, 2 stages
constexpr int PADG = 36;           // 32 data + 4 pad u32
constexpr int KC2  = 32;           // chunk size in u32
constexpr int NC2  = Dh / KC2;     // 12 chunks
constexpr int A2_U32   = 256 * PADG;        // 9216
constexpr int B2_U32   = 128 * PADG;        // 4608
constexpr int STG2_U32 = A2_U32 + B2_U32;   // 13824 (55296 B)
constexpr int GEMM_SMEM = 2 * STG2_U32 * 4; // 110592 B

// Attn: 128-key stages (two 64-key compute halves), 2-stage pipeline, 256 thr
constexpr int AK2   = 128 * 36;             // K tile: 128 keys x (32+4) u32
constexpr int AV2   = 64 * 68;              // Vt tile: 64 d x (64+4) u32
constexpr int ASTG2 = AK2 + AV2;            // 8960 u32 (35840 B)
constexpr int ATTN_SMEM = 2 * ASTG2 * 4;    // 71680 B
constexpr int NCT2  = T / 128;              // 16 stages

// Scratch (__device__ globals; fp16 storage packed as uint32 = half2)
__device__ uint32_t g_xh[BT * Dh];
__device__ uint32_t g_wq[NQKV * Dh];
__device__ uint32_t g_wo[D * Dh];
__device__ uint32_t g_Q[B * H * T * (HD / 2)];   // Q pre-scaled by 1/16
__device__ uint32_t g_K[B * H * T * (HD / 2)];
__device__ __half   g_Vt[(size_t)B * H * HD * T];   // V transposed: [b][h][d][t]
__device__ uint32_t g_att[BT * Dh];
__device__ float    g_mag[BT];

__device__ __forceinline__ uint32_t h2(float lo, float hi) {
    uint32_t u;  // first asm source -> upper 16 bits
    asm("cvt.rn.f16x2.f32 %0, %1, %2;" : "=r"(u) : "f"(hi), "f"(lo));
    return u;
}
__device__ __forceinline__ void mma16(float c[4], const uint32_t a[4], const uint32_t b[2]) {
    asm volatile(
        "mma.sync.aligned.m16n8k16.row.col.f32.f16.f16.f32 "
        "{%0,%1,%2,%3}, {%4,%5,%6,%7}, {%8,%9}, {%0,%1,%2,%3};"
        : "+f"(c[0]), "+f"(c[1]), "+f"(c[2]), "+f"(c[3])
        : "r"(a[0]), "r"(a[1]), "r"(a[2]), "r"(a[3]), "r"(b[0]), "r"(b[1]));
}
__device__ __forceinline__ uint32_t saddr(const void* p) {
    return (uint32_t)__cvta_generic_to_shared(p);
}
__device__ __forceinline__ void ldsm4(uint32_t* r, uint32_t a) {
    asm volatile("ldmatrix.sync.aligned.m8n8.x4.shared.b16 {%0,%1,%2,%3}, [%4];"
                 : "=r"(r[0]), "=r"(r[1]), "=r"(r[2]), "=r"(r[3]) : "r"(a));
}
__device__ __forceinline__ void cp16(uint32_t s, const void* g) {
    asm volatile("cp.async.cg.shared.global [%0], [%1], 16;" :: "r"(s), "l"(g));
}
__device__ __forceinline__ void cp_commit() {
    asm volatile("cp.async.commit_group;" ::: "memory");
}
template <int N>
__device__ __forceinline__ void cp_wait() {
    asm volatile("cp.async.wait_group %0;" :: "n"(N) : "memory");
}

// ---------------------------------------------------------------------------
// Kernel 1: warp-per-row. weight row-norm -> fp16; x -> fp16 + magnitude.
// ---------------------------------------------------------------------------
__global__ void __launch_bounds__(256) prep_kernel(const float* __restrict__ x,
                                                   const float* __restrict__ qkv_w,
                                                   const float* __restrict__ out_w) {
    const int row = blockIdx.x * 8 + (threadIdx.x >> 5);
    const int lane = threadIdx.x & 31;
    const float* src;
    uint32_t* dst;
    float* magdst = nullptr;
    bool donorm = true;
    if (row < NQKV) {
        src = qkv_w + (size_t)row * D;  dst = g_wq + (size_t)row * Dh;
    } else if (row < NQKV + D) {
        src = out_w + (size_t)(row - NQKV) * D;  dst = g_wo + (size_t)(row - NQKV) * Dh;
    } else {
        const int tr = row - (NQKV + D);
        src = x + (size_t)tr * D;  dst = g_xh + (size_t)tr * Dh;
        magdst = g_mag + tr;  donorm = false;
    }
    float4 v[6];
    float s = 0.f;
#pragma unroll
    for (int j = 0; j < 6; j++) {
        v[j] = ((const float4*)src)[lane + j * 32];
        s += v[j].x * v[j].x + v[j].y * v[j].y + v[j].z * v[j].z + v[j].w * v[j].w;
    }
#pragma unroll
    for (int o = 16; o > 0; o >>= 1) s += __shfl_xor_sync(0xffffffffu, s, o);
    if (donorm) {
        const float inv = 1.0f / (sqrtf(s) + EPS);
#pragma unroll
        for (int j = 0; j < 6; j++) {
            dst[2 * (lane + j * 32)]     = h2(v[j].x * inv, v[j].y * inv);
            dst[2 * (lane + j * 32) + 1] = h2(v[j].z * inv, v[j].w * inv);
        }
    } else {
#pragma unroll
        for (int j = 0; j < 6; j++) {
            dst[2 * (lane + j * 32)]     = h2(v[j].x, v[j].y);
            dst[2 * (lane + j * 32) + 1] = h2(v[j].z, v[j].w);
        }
        if (lane == 0) magdst[0] = sqrtf(s) * (1.0f / sqrtf((float)D));
    }
}

// ---------------------------------------------------------------------------
// fp16 GEMM core: 256x128 tile, 512 threads (16 warps = 8m x 2n), warp tile
// 32x64, 64-half chunks, 2-stage cp.async pipeline, 1 barrier/chunk.
// ---------------------------------------------------------------------------
__device__ __forceinline__ void gemm_core(const uint32_t* __restrict__ A,
                                          const uint32_t* __restrict__ W,
                                          int m0, int n0, uint32_t* sm,
                                          float (&acc)[2][8][4], int tid) {
    const int lane = tid & 31, warp = tid >> 5;
    const int wm = warp >> 1, wn = warp & 1;      // wm 0..7, wn 0..1
    const uint32_t* Ab = A + (size_t)m0 * Dh;
    const uint32_t* Wb = W + (size_t)n0 * Dh;
    const uint32_t sb = saddr(sm);

    const uint32_t a_off = ((wm * 32 + (lane & 15)) * PADG + (lane >> 4) * 4) << 2;
    const uint32_t b_off = (A2_U32 + (wn * 64 + ((lane >> 4) & 1) * 8 + (lane & 7)) * PADG +
                            ((lane >> 3) & 1) * 4) << 2;

    auto stage = [&](int s, int c) {
        const uint32_t base = sb + (uint32_t)(s * STG2_U32) * 4;
        const int k0 = c * KC2;
#pragma unroll
        for (int j = 0; j < 4; j++) {            // A: 256 rows x 8 segs of 16B
            const int idx = tid + j * 512;
            const int row = idx >> 3, seg = idx & 7;
            cp16(base + ((row * PADG + seg * 4) << 2), Ab + (size_t)row * Dh + k0 + seg * 4);
        }
#pragma unroll
        for (int j = 0; j < 2; j++) {            // B: 128 rows x 8 segs of 16B
            const int idx = tid + j * 512;
            const int row = idx >> 3, seg = idx & 7;
            cp16(base + ((A2_U32 + row * PADG + seg * 4) << 2), Wb + (size_t)row * Dh + k0 + seg * 4);
        }
        cp_commit();
    };

    stage(0, 0);
    for (int k = 0; k < NC2; k++) {
        cp_wait<0>();
        __syncthreads();
        if (k + 1 < NC2) stage((k + 1) & 1, k + 1);   // overlaps compute below
        const uint32_t base = sb + (uint32_t)((k & 1) * STG2_U32) * 4;
#pragma unroll
        for (int ks = 0; ks < 4; ks++) {
            const uint32_t kk4 = (ks * 8) << 2;
            uint32_t af[2][4], bq[4][4];
            ldsm4(af[0], base + a_off + kk4);
            ldsm4(af[1], base + a_off + ((16 * PADG) << 2) + kk4);
#pragma unroll
            for (int np = 0; np < 4; np++)
                ldsm4(bq[np], base + b_off + ((np * 16 * PADG) << 2) + kk4);
#pragma unroll
            for (int mt = 0; mt < 2; mt++)
#pragma unroll
                for (int np = 0; np < 4; np++) {
                    mma16(acc[mt][2 * np],     af[mt], bq[np]);
                    mma16(acc[mt][2 * np + 1], af[mt], bq[np] + 2);
                }
        }
    }
}

// ---------------------------------------------------------------------------
// Kernel 2: qkv GEMM (256x128) + warp-local per-head q/k RMS-normalize.
// Q stored PRE-SCALED by 1/16 (folds sigmoid arg scale). V transposed via smem.
// grid: (2304/128, 8192/256), 512 threads.
// ---------------------------------------------------------------------------
__global__ void __launch_bounds__(512, 1) qkv_mm() {
    extern __shared__ __align__(16) uint32_t dsm[];
    const int n0 = blockIdx.x * 128, m0 = blockIdx.y * 256;
    const int tid = threadIdx.x, lane = tid & 31, warp = tid >> 5;
    const int wm = warp >> 1, wn = warp & 1, g = lane >> 2, c = lane & 3;

    float acc[2][8][4] = {};
    gemm_core(g_xh, g_wq, m0, n0, dsm, acc, tid);

    const int which = n0 / D;                      // 0=q 1=k 2=v
    const int headbase = (n0 % D) >> 6;
    const int b = m0 / T;

    if (which < 2) {
        const int head = headbase + wn;
        uint32_t* dstb = (which == 0) ? g_Q : g_K;
        const float nrm = (which == 0) ? 0.5f : 8.0f;   // q: 8/16 folded
#pragma unroll
        for (int mt = 0; mt < 2; mt++) {
            float s0 = 0.f, s1 = 0.f;
#pragma unroll
            for (int nt = 0; nt < 8; nt++) {
                s0 += acc[mt][nt][0] * acc[mt][nt][0] + acc[mt][nt][1] * acc[mt][nt][1];
                s1 += acc[mt][nt][2] * acc[mt][nt][2] + acc[mt][nt][3] * acc[mt][nt][3];
            }
            s0 += __shfl_xor_sync(~0u, s0, 1); s0 += __shfl_xor_sync(~0u, s0, 2);
            s1 += __shfl_xor_sync(~0u, s1, 1); s1 += __shfl_xor_sync(~0u, s1, 2);
            const float sc[2] = {nrm / (sqrtf(s0) + EPS), nrm / (sqrtf(s1) + EPS)};
#pragma unroll
            for (int rr = 0; rr < 2; rr++) {
                const int t = (m0 + wm * 32 + mt * 16 + g + rr * 8) & (T - 1);
                uint32_t* dp = dstb + (((size_t)(b * H + head)) * T + t) * (HD / 2);
#pragma unroll
                for (int nt = 0; nt < 8; nt++)
                    dp[nt * 4 + c] = h2(acc[mt][nt][rr * 2] * sc[rr],
                                        acc[mt][nt][rr * 2 + 1] * sc[rr]);
            }
        }
    } else {
        // V: transpose via smem, then coalesced row writes to g_Vt.
        __syncthreads();                           // last chunk's ldsm reads done
        __half* Vsm = (__half*)dsm;                // [128 d][264 halfs]
#pragma unroll
        for (int mt = 0; mt < 2; mt++)
#pragma unroll
            for (int rr = 0; rr < 2; rr++) {
                const int tl = wm * 32 + mt * 16 + g + rr * 8;
#pragma unroll
                for (int nt = 0; nt < 8; nt++) {
                    const int d0 = wn * 64 + nt * 8 + 2 * c;
                    Vsm[d0 * 264 + tl]       = __float2half(acc[mt][nt][rr * 2]);
                    Vsm[(d0 + 1) * 264 + tl] = __float2half(acc[mt][nt][rr * 2 + 1]);
                }
            }
        __syncthreads();
        const int col = tid & 127;                 // d_local (2 heads x 64)
        const int qtr = tid >> 7;                  // t quarter (0..3)
        const int head = headbase + (col >> 6);
        const int dd = col & 63;
        const int t0 = (m0 & (T - 1)) + qtr * 64;
        const uint4* srcv = (const uint4*)(Vsm + col * 264 + qtr * 64);
        uint4* dstv = (uint4*)(g_Vt + ((size_t)(b * H + head) * HD + dd) * T + t0);
#pragma unroll
        for (int j = 0; j < 8; j++) dstv[j] = srcv[j];
    }
}

// ---------------------------------------------------------------------------
// Kernel 3: fused sigmoid attention. Q pre-scaled by 1/16 -> sacc is the tanh
// argument directly. 128-key 2-stage pipeline. grid: (T/128, H, B), 256 thr.
// ---------------------------------------------------------------------------
__global__ void __launch_bounds__(256) attn_mma() {
    extern __shared__ __align__(16) uint32_t dsm[];
    const int tid = threadIdx.x, lane = tid & 31, warp = tid >> 5;
    const int g = lane >> 2, c = lane & 3;
    const int q0 = blockIdx.x * 128;
    const int h = blockIdx.y, b = blockIdx.z;
    const size_t bh = ((size_t)(b * H + h)) * T;

    uint32_t qf[4][4];
    {
        const uint32_t* Qg = g_Q + (bh + q0 + warp * 16) * (HD / 2);
#pragma unroll
        for (int ks = 0; ks < 4; ks++) {
            qf[ks][0] = Qg[(size_t)g * 32 + ks * 8 + c];
            qf[ks][1] = Qg[(size_t)(g + 8) * 32 + ks * 8 + c];
            qf[ks][2] = Qg[(size_t)g * 32 + ks * 8 + c + 4];
            qf[ks][3] = Qg[(size_t)(g + 8) * 32 + ks * 8 + c + 4];
        }
    }

    const uint32_t sb = saddr(dsm);
    const uint32_t krow = ((lane >> 4) & 1) * 8 + (lane & 7);
    const uint32_t kcol = ((lane >> 3) & 1) * 4;
    const uint32_t kb_off = (krow * 36 + kcol) << 2;
    const uint32_t vb_off = (AK2 + krow * 68 + kcol) << 2;

    const uint32_t* Kg0  = g_K + bh * (HD / 2);
    const uint32_t* Vtg0 = (const uint32_t*)(g_Vt + bh * HD);  // rows of T/2 uint32

    auto stage_kv = [&](int s, int i) {
        const uint32_t base = sb + (uint32_t)(s * ASTG2) * 4;
#pragma unroll
        for (int j = 0; j < 4; j++) {              // K: 128 rows x 8 segs
            const int idx = tid + j * 256;
            const int row = idx >> 3, seg = idx & 7;
            cp16(base + ((row * 36 + seg * 4) << 2),
                 Kg0 + (size_t)(i * 128 + row) * 32 + seg * 4);
        }
#pragma unroll
        for (int j = 0; j < 4; j++) {              // Vt: 64 rows x 16 segs
            const int idx = tid + j * 256;
            const int row = idx >> 4, seg = idx & 15;
            cp16(base + ((AK2 + row * 68 + seg * 4) << 2),
                 Vtg0 + (size_t)row * (T / 2) + i * 64 + seg * 4);
        }
        cp_commit();
    };

    float oacc[8][4] = {};

    stage_kv(0, 0);
    for (int i = 0; i < NCT2; i++) {
        cp_wait<0>();
        __syncthreads();
        if (i + 1 < NCT2) stage_kv((i + 1) & 1, i + 1);
        const uint32_t base = sb + (uint32_t)((i & 1) * ASTG2) * 4;

#pragma unroll
        for (int hh = 0; hh < 2; hh++) {
            // S = (Q/16) K^T  (16 x 64 per warp) == tanh argument
            float sacc[8][4] = {};
#pragma unroll
            for (int ks = 0; ks < 4; ks++) {
                uint32_t bq[4][4];
#pragma unroll
                for (int np = 0; np < 4; np++)
                    ldsm4(bq[np], base + kb_off + (((hh * 64 + np * 16) * 36 + ks * 8) << 2));
#pragma unroll
                for (int np = 0; np < 4; np++) {
                    mma16(sacc[2 * np],     qf[ks], bq[np]);
                    mma16(sacc[2 * np + 1], qf[ks], bq[np] + 2);
                }
            }
            // O += sigmoid V : pack, tanh.f16x2, .5t+.5, mma
#pragma unroll
            for (int kt = 0; kt < 4; kt++) {
                uint32_t af[4];
                af[0] = h2(sacc[2 * kt][0],     sacc[2 * kt][1]);
                af[1] = h2(sacc[2 * kt][2],     sacc[2 * kt][3]);
                af[2] = h2(sacc[2 * kt + 1][0], sacc[2 * kt + 1][1]);
                af[3] = h2(sacc[2 * kt + 1][2], sacc[2 * kt + 1][3]);
#pragma unroll
                for (int j = 0; j < 4; j++) {
                    asm("tanh.approx.f16x2 %0, %0;" : "+r"(af[j]));
                    asm("fma.rn.f16x2 %0, %0, %1, %1;" : "+r"(af[j]) : "r"(0x38003800u));
                }
                uint32_t bq[4][4];
#pragma unroll
                for (int np = 0; np < 4; np++)
                    ldsm4(bq[np], base + vb_off + ((np * 16 * 68 + hh * 32 + kt * 8) << 2));
#pragma unroll
                for (int np = 0; np < 4; np++) {
                    mma16(oacc[2 * np],     af, bq[np]);
                    mma16(oacc[2 * np + 1], af, bq[np] + 2);
                }
            }
        }
    }

    const float cst = GAIN * rsqrtf((float)T);
#pragma unroll
    for (int rr = 0; rr < 2; rr++) {
        float s = 0.f;
#pragma unroll
        for (int nt = 0; nt < 8; nt++)
            s += oacc[nt][rr * 2] * oacc[nt][rr * 2] + oacc[nt][rr * 2 + 1] * oacc[nt][rr * 2 + 1];
        s += __shfl_xor_sync(~0u, s, 1);
        s += __shfl_xor_sync(~0u, s, 2);
        const int t = q0 + warp * 16 + g + rr * 8;
        const float n = cst * sqrtf(s);
        const float f = 8.0f * cst * g_mag[b * T + t] / (n + EPS);
        uint32_t* dp = g_att + ((size_t)b * T + t) * Dh + h * (HD / 2);
#pragma unroll
        for (int nt = 0; nt < 8; nt++)
            dp[nt * 4 + c] = h2(oacc[nt][rr * 2] * f, oacc[nt][rr * 2 + 1] * f);
    }
}

// ---------------------------------------------------------------------------
// Kernel 4: out-projection (256x128)  y = att @ wn_out^T  (fp32 out)
// grid: (768/128, 8192/256), 512 threads.
// ---------------------------------------------------------------------------
__global__ void __launch_bounds__(512, 1) proj_mm(float* __restrict__ out) {
    extern __shared__ __align__(16) uint32_t dsm[];
    const int n0 = blockIdx.x * 128, m0 = blockIdx.y * 256;
    const int tid = threadIdx.x, lane = tid & 31, warp = tid >> 5;
    const int wm = warp >> 1, wn = warp & 1, g = lane >> 2, c = lane & 3;

    float acc[2][8][4] = {};
    gemm_core(g_att, g_wo, m0, n0, dsm, acc, tid);

#pragma unroll
    for (int mt = 0; mt < 2; mt++) {
#pragma unroll
        for (int rr = 0; rr < 2; rr++) {
            const int m = m0 + wm * 32 + mt * 16 + g + rr * 8;
            float* dp = out + (size_t)m * D + n0 + wn * 64;
#pragma unroll
            for (int nt = 0; nt < 8; nt++) {
                const int col = nt * 8 + 2 * c;
                *(float2*)&dp[col] = make_float2(acc[mt][nt][rr * 2],
                                                 acc[mt][nt][rr * 2 + 1]);
            }
        }
    }
}

// ---------------------------------------------------------------------------
extern "C" void kernel_launch(void* const* d_in, const int* in_sizes, int n_in,
                              void* d_out, int out_size) {
    const float* x     = (const float*)d_in[0];
    const float* qkv_w = (const float*)d_in[1];
    const float* out_w = (const float*)d_in[2];

    cudaFuncSetAttribute(qkv_mm, cudaFuncAttributeMaxDynamicSharedMemorySize, GEMM_SMEM);
    cudaFuncSetAttribute(proj_mm, cudaFuncAttributeMaxDynamicSharedMemorySize, GEMM_SMEM);
    cudaFuncSetAttribute(attn_mma, cudaFuncAttributeMaxDynamicSharedMemorySize, ATTN_SMEM);

    prep_kernel<<<(NQKV + D + BT) / 8, 256>>>(x, qkv_w, out_w);
    qkv_mm<<<dim3(NQKV / 128, BT / 256), 512, GEMM_SMEM>>>();
    attn_mma<<<dim3(T / 128, H, B), 256, ATTN_SMEM>>>();
    proj_mm<<<dim3(D / 128, BT / 256), 512, GEMM_SMEM>>>((float*)d_out);
}

// round 13
// speedup vs baseline: 1.0588x; 1.0588x over previous
#include <cuda_runtime.h>
#include <cuda_fp16.h>
#include <math.h>
#include <stdint.h>

// Problem constants
constexpr int B  = 4;
constexpr int T  = 2048;
constexpr int D  = 768;
constexpr int H  = 12;
constexpr int HD = 64;
constexpr int BT = B * T;          // 8192
constexpr int NQKV = 3 * D;        // 2304
constexpr float EPS  = 1e-4f;
constexpr float GAIN = 1.8402f;

constexpr int Dh   = D / 2;        // 384 uint32 (half2) per row

// GEMM: 128x128 tile, 256 threads (8 warps = 4m x 2n), 64-half chunks, 2 stages
constexpr int PADG = 36;           // 32 data + 4 pad u32
constexpr int KC2  = 32;           // chunk size in u32
constexpr int NC2  = Dh / KC2;     // 12 chunks
constexpr int A2_U32   = 128 * PADG;        // 4608
constexpr int STG2_U32 = 2 * A2_U32;        // 9216 (36864 B)
constexpr int GEMM_SMEM = 2 * STG2_U32 * 4; // 73728 B

// Attn: 128-key stages (two 64-key compute halves), 2-stage pipeline, 256 thr
constexpr int AK2   = 128 * 36;             // K tile: 128 keys x (32+4) u32
constexpr int AV2   = 64 * 68;              // Vt tile: 64 d x (64+4) u32
constexpr int ASTG2 = AK2 + AV2;            // 8960 u32 (35840 B)
constexpr int ATTN_SMEM = 2 * ASTG2 * 4;    // 71680 B
constexpr int NCT2  = T / 128;              // 16 stages

// Scratch (__device__ globals; fp16 storage packed as uint32 = half2)
__device__ uint32_t g_xh[BT * Dh];
__device__ uint32_t g_wq[NQKV * Dh];
__device__ uint32_t g_wo[D * Dh];
__device__ uint32_t g_Q[B * H * T * (HD / 2)];   // Q pre-scaled by 1/16
__device__ uint32_t g_K[B * H * T * (HD / 2)];
__device__ __half   g_Vt[(size_t)B * H * HD * T];   // V transposed: [b][h][d][t]
__device__ uint32_t g_att[BT * Dh];
__device__ float    g_mag[BT];

__device__ __forceinline__ uint32_t h2(float lo, float hi) {
    uint32_t u;  // first asm source -> upper 16 bits
    asm("cvt.rn.f16x2.f32 %0, %1, %2;" : "=r"(u) : "f"(hi), "f"(lo));
    return u;
}
__device__ __forceinline__ void mma16(float c[4], const uint32_t a[4], const uint32_t b[2]) {
    asm volatile(
        "mma.sync.aligned.m16n8k16.row.col.f32.f16.f16.f32 "
        "{%0,%1,%2,%3}, {%4,%5,%6,%7}, {%8,%9}, {%0,%1,%2,%3};"
        : "+f"(c[0]), "+f"(c[1]), "+f"(c[2]), "+f"(c[3])
        : "r"(a[0]), "r"(a[1]), "r"(a[2]), "r"(a[3]), "r"(b[0]), "r"(b[1]));
}
__device__ __forceinline__ uint32_t saddr(const void* p) {
    return (uint32_t)__cvta_generic_to_shared(p);
}
__device__ __forceinline__ void ldsm4(uint32_t* r, uint32_t a) {
    asm volatile("ldmatrix.sync.aligned.m8n8.x4.shared.b16 {%0,%1,%2,%3}, [%4];"
                 : "=r"(r[0]), "=r"(r[1]), "=r"(r[2]), "=r"(r[3]) : "r"(a));
}
__device__ __forceinline__ void cp16(uint32_t s, const void* g) {
    asm volatile("cp.async.cg.shared.global [%0], [%1], 16;" :: "r"(s), "l"(g));
}
__device__ __forceinline__ void cp_commit() {
    asm volatile("cp.async.commit_group;" ::: "memory");
}
template <int N>
__device__ __forceinline__ void cp_wait() {
    asm volatile("cp.async.wait_group %0;" :: "n"(N) : "memory");
}

// ---------------------------------------------------------------------------
// Kernel 1: warp-per-row. weight row-norm -> fp16; x -> fp16 + magnitude.
// ---------------------------------------------------------------------------
__global__ void __launch_bounds__(256) prep_kernel(const float* __restrict__ x,
                                                   const float* __restrict__ qkv_w,
                                                   const float* __restrict__ out_w) {
    const int row = blockIdx.x * 8 + (threadIdx.x >> 5);
    const int lane = threadIdx.x & 31;
    const float* src;
    uint32_t* dst;
    float* magdst = nullptr;
    bool donorm = true;
    if (row < NQKV) {
        src = qkv_w + (size_t)row * D;  dst = g_wq + (size_t)row * Dh;
    } else if (row < NQKV + D) {
        src = out_w + (size_t)(row - NQKV) * D;  dst = g_wo + (size_t)(row - NQKV) * Dh;
    } else {
        const int tr = row - (NQKV + D);
        src = x + (size_t)tr * D;  dst = g_xh + (size_t)tr * Dh;
        magdst = g_mag + tr;  donorm = false;
    }
    float4 v[6];
    float s = 0.f;
#pragma unroll
    for (int j = 0; j < 6; j++) {
        v[j] = ((const float4*)src)[lane + j * 32];
        s += v[j].x * v[j].x + v[j].y * v[j].y + v[j].z * v[j].z + v[j].w * v[j].w;
    }
#pragma unroll
    for (int o = 16; o > 0; o >>= 1) s += __shfl_xor_sync(0xffffffffu, s, o);
    if (donorm) {
        const float inv = 1.0f / (sqrtf(s) + EPS);
#pragma unroll
        for (int j = 0; j < 6; j++) {
            dst[2 * (lane + j * 32)]     = h2(v[j].x * inv, v[j].y * inv);
            dst[2 * (lane + j * 32) + 1] = h2(v[j].z * inv, v[j].w * inv);
        }
    } else {
#pragma unroll
        for (int j = 0; j < 6; j++) {
            dst[2 * (lane + j * 32)]     = h2(v[j].x, v[j].y);
            dst[2 * (lane + j * 32) + 1] = h2(v[j].z, v[j].w);
        }
        if (lane == 0) magdst[0] = sqrtf(s) * (1.0f / sqrtf((float)D));
    }
}

// ---------------------------------------------------------------------------
// fp16 GEMM core: 128x128 tile, 64-half chunks, 2-stage cp.async pipeline.
// 8 warps (4m x 2n), warp tile 32x64. One __syncthreads per chunk (12 total).
// ---------------------------------------------------------------------------
__device__ __forceinline__ void gemm_core(const uint32_t* __restrict__ A,
                                          const uint32_t* __restrict__ W,
                                          int m0, int n0, uint32_t* sm,
                                          float (&acc)[2][8][4], int tid) {
    const int lane = tid & 31, warp = tid >> 5;
    const int wm = warp >> 1, wn = warp & 1;
    const uint32_t* Ab = A + (size_t)m0 * Dh;
    const uint32_t* Wb = W + (size_t)n0 * Dh;
    const uint32_t sb = saddr(sm);

    const uint32_t a_off = ((wm * 32 + (lane & 15)) * PADG + (lane >> 4) * 4) << 2;
    const uint32_t b_off = (A2_U32 + (wn * 64 + ((lane >> 4) & 1) * 8 + (lane & 7)) * PADG +
                            ((lane >> 3) & 1) * 4) << 2;

    auto stage = [&](int s, int c) {
        const uint32_t base = sb + (uint32_t)(s * STG2_U32) * 4;
        const int k0 = c * KC2;
#pragma unroll
        for (int j = 0; j < 4; j++) {            // A: 128 rows x 8 segs of 16B
            const int idx = tid + j * 256;
            const int row = idx >> 3, seg = idx & 7;
            cp16(base + ((row * PADG + seg * 4) << 2), Ab + (size_t)row * Dh + k0 + seg * 4);
        }
#pragma unroll
        for (int j = 0; j < 4; j++) {            // B: 128 rows x 8 segs of 16B
            const int idx = tid + j * 256;
            const int row = idx >> 3, seg = idx & 7;
            cp16(base + ((A2_U32 + row * PADG + seg * 4) << 2), Wb + (size_t)row * Dh + k0 + seg * 4);
        }
        cp_commit();
    };

    stage(0, 0);
    for (int k = 0; k < NC2; k++) {
        cp_wait<0>();
        __syncthreads();
        if (k + 1 < NC2) stage((k + 1) & 1, k + 1);   // overlaps compute below
        const uint32_t base = sb + (uint32_t)((k & 1) * STG2_U32) * 4;
#pragma unroll
        for (int ks = 0; ks < 4; ks++) {
            const uint32_t kk4 = (ks * 8) << 2;
            uint32_t af[2][4], bq[4][4];
            ldsm4(af[0], base + a_off + kk4);
            ldsm4(af[1], base + a_off + ((16 * PADG) << 2) + kk4);
#pragma unroll
            for (int np = 0; np < 4; np++)
                ldsm4(bq[np], base + b_off + ((np * 16 * PADG) << 2) + kk4);
#pragma unroll
            for (int mt = 0; mt < 2; mt++)
#pragma unroll
                for (int np = 0; np < 4; np++) {
                    mma16(acc[mt][2 * np],     af[mt], bq[np]);
                    mma16(acc[mt][2 * np + 1], af[mt], bq[np] + 2);
                }
        }
    }
}

// ---------------------------------------------------------------------------
// Kernel 2: qkv GEMM + warp-local per-head q/k RMS-normalize + scatter.
// Q stored PRE-SCALED by 1/16 (folds sigmoid arg scale). V transposed via smem.
// grid: (2304/128, 8192/128), 256 threads.
// ---------------------------------------------------------------------------
__global__ void __launch_bounds__(256, 2) qkv_mm() {
    extern __shared__ __align__(16) uint32_t dsm[];
    const int n0 = blockIdx.x * 128, m0 = blockIdx.y * 128;
    const int tid = threadIdx.x, lane = tid & 31, warp = tid >> 5;
    const int wm = warp >> 1, wn = warp & 1, g = lane >> 2, c = lane & 3;

    float acc[2][8][4] = {};
    gemm_core(g_xh, g_wq, m0, n0, dsm, acc, tid);

    const int which = n0 / D;                      // 0=q 1=k 2=v
    const int headbase = (n0 % D) >> 6;
    const int b = m0 / T;

    if (which < 2) {
        const int head = headbase + wn;
        uint32_t* dstb = (which == 0) ? g_Q : g_K;
        const float nrm = (which == 0) ? 0.5f : 8.0f;   // q: 8/16 folded
#pragma unroll
        for (int mt = 0; mt < 2; mt++) {
            float s0 = 0.f, s1 = 0.f;
#pragma unroll
            for (int nt = 0; nt < 8; nt++) {
                s0 += acc[mt][nt][0] * acc[mt][nt][0] + acc[mt][nt][1] * acc[mt][nt][1];
                s1 += acc[mt][nt][2] * acc[mt][nt][2] + acc[mt][nt][3] * acc[mt][nt][3];
            }
            s0 += __shfl_xor_sync(~0u, s0, 1); s0 += __shfl_xor_sync(~0u, s0, 2);
            s1 += __shfl_xor_sync(~0u, s1, 1); s1 += __shfl_xor_sync(~0u, s1, 2);
            const float sc[2] = {nrm / (sqrtf(s0) + EPS), nrm / (sqrtf(s1) + EPS)};
#pragma unroll
            for (int rr = 0; rr < 2; rr++) {
                const int t = (m0 + wm * 32 + mt * 16 + g + rr * 8) & (T - 1);
                uint32_t* dp = dstb + (((size_t)(b * H + head)) * T + t) * (HD / 2);
#pragma unroll
                for (int nt = 0; nt < 8; nt++)
                    dp[nt * 4 + c] = h2(acc[mt][nt][rr * 2] * sc[rr],
                                        acc[mt][nt][rr * 2 + 1] * sc[rr]);
            }
        }
    } else {
        // V: transpose via smem, then coalesced row writes to g_Vt.
        __syncthreads();                           // last chunk's ldsm reads done
        __half* Vsm = (__half*)dsm;                // [128 d][136 halfs]
#pragma unroll
        for (int mt = 0; mt < 2; mt++)
#pragma unroll
            for (int rr = 0; rr < 2; rr++) {
                const int tl = wm * 32 + mt * 16 + g + rr * 8;
#pragma unroll
                for (int nt = 0; nt < 8; nt++) {
                    const int d0 = wn * 64 + nt * 8 + 2 * c;
                    Vsm[d0 * 136 + tl]       = __float2half(acc[mt][nt][rr * 2]);
                    Vsm[(d0 + 1) * 136 + tl] = __float2half(acc[mt][nt][rr * 2 + 1]);
                }
            }
        __syncthreads();
        const int col = tid & 127;                 // d_local (2 heads x 64)
        const int hf = tid >> 7;                   // t half
        const int head = headbase + (col >> 6);
        const int dd = col & 63;
        const int t0 = (m0 & (T - 1)) + hf * 64;
        const uint4* srcv = (const uint4*)(Vsm + col * 136 + hf * 64);
        uint4* dstv = (uint4*)(g_Vt + ((size_t)(b * H + head) * HD + dd) * T + t0);
#pragma unroll
        for (int j = 0; j < 8; j++) dstv[j] = srcv[j];
    }
}

// ---------------------------------------------------------------------------
// Kernel 3: fused sigmoid attention. Q pre-scaled by 1/16 -> sacc is the tanh
// argument directly. 128-key 2-stage pipeline. grid: (T/128, H, B), 256 thr.
// ---------------------------------------------------------------------------
__global__ void __launch_bounds__(256) attn_mma() {
    extern __shared__ __align__(16) uint32_t dsm[];
    const int tid = threadIdx.x, lane = tid & 31, warp = tid >> 5;
    const int g = lane >> 2, c = lane & 3;
    const int q0 = blockIdx.x * 128;
    const int h = blockIdx.y, b = blockIdx.z;
    const size_t bh = ((size_t)(b * H + h)) * T;

    uint32_t qf[4][4];
    {
        const uint32_t* Qg = g_Q + (bh + q0 + warp * 16) * (HD / 2);
#pragma unroll
        for (int ks = 0; ks < 4; ks++) {
            qf[ks][0] = Qg[(size_t)g * 32 + ks * 8 + c];
            qf[ks][1] = Qg[(size_t)(g + 8) * 32 + ks * 8 + c];
            qf[ks][2] = Qg[(size_t)g * 32 + ks * 8 + c + 4];
            qf[ks][3] = Qg[(size_t)(g + 8) * 32 + ks * 8 + c + 4];
        }
    }

    const uint32_t sb = saddr(dsm);
    const uint32_t krow = ((lane >> 4) & 1) * 8 + (lane & 7);
    const uint32_t kcol = ((lane >> 3) & 1) * 4;
    const uint32_t kb_off = (krow * 36 + kcol) << 2;
    const uint32_t vb_off = (AK2 + krow * 68 + kcol) << 2;

    const uint32_t* Kg0  = g_K + bh * (HD / 2);
    const uint32_t* Vtg0 = (const uint32_t*)(g_Vt + bh * HD);  // rows of T/2 uint32

    auto stage_kv = [&](int s, int i) {
        const uint32_t base = sb + (uint32_t)(s * ASTG2) * 4;
#pragma unroll
        for (int j = 0; j < 4; j++) {              // K: 128 rows x 8 segs
            const int idx = tid + j * 256;
            const int row = idx >> 3, seg = idx & 7;
            cp16(base + ((row * 36 + seg * 4) << 2),
                 Kg0 + (size_t)(i * 128 + row) * 32 + seg * 4);
        }
#pragma unroll
        for (int j = 0; j < 4; j++) {              // Vt: 64 rows x 16 segs
            const int idx = tid + j * 256;
            const int row = idx >> 4, seg = idx & 15;
            cp16(base + ((AK2 + row * 68 + seg * 4) << 2),
                 Vtg0 + (size_t)row * (T / 2) + i * 64 + seg * 4);
        }
        cp_commit();
    };

    float oacc[8][4] = {};

    stage_kv(0, 0);
    for (int i = 0; i < NCT2; i++) {
        cp_wait<0>();
        __syncthreads();
        if (i + 1 < NCT2) stage_kv((i + 1) & 1, i + 1);
        const uint32_t base = sb + (uint32_t)((i & 1) * ASTG2) * 4;

#pragma unroll
        for (int hh = 0; hh < 2; hh++) {
            // S = (Q/16) K^T  (16 x 64 per warp) == tanh argument
            float sacc[8][4] = {};
#pragma unroll
            for (int ks = 0; ks < 4; ks++) {
                uint32_t bq[4][4];
#pragma unroll
                for (int np = 0; np < 4; np++)
                    ldsm4(bq[np], base + kb_off + (((hh * 64 + np * 16) * 36 + ks * 8) << 2));
#pragma unroll
                for (int np = 0; np < 4; np++) {
                    mma16(sacc[2 * np],     qf[ks], bq[np]);
                    mma16(sacc[2 * np + 1], qf[ks], bq[np] + 2);
                }
            }
            // O += sigmoid V : pack, tanh.f16x2, .5t+.5, mma
#pragma unroll
            for (int kt = 0; kt < 4; kt++) {
                uint32_t af[4];
                af[0] = h2(sacc[2 * kt][0],     sacc[2 * kt][1]);
                af[1] = h2(sacc[2 * kt][2],     sacc[2 * kt][3]);
                af[2] = h2(sacc[2 * kt + 1][0], sacc[2 * kt + 1][1]);
                af[3] = h2(sacc[2 * kt + 1][2], sacc[2 * kt + 1][3]);
#pragma unroll
                for (int j = 0; j < 4; j++) {
                    asm("tanh.approx.f16x2 %0, %0;" : "+r"(af[j]));
                    asm("fma.rn.f16x2 %0, %0, %1, %1;" : "+r"(af[j]) : "r"(0x38003800u));
                }
                uint32_t bq[4][4];
#pragma unroll
                for (int np = 0; np < 4; np++)
                    ldsm4(bq[np], base + vb_off + ((np * 16 * 68 + hh * 32 + kt * 8) << 2));
#pragma unroll
                for (int np = 0; np < 4; np++) {
                    mma16(oacc[2 * np],     af, bq[np]);
                    mma16(oacc[2 * np + 1], af, bq[np] + 2);
                }
            }
        }
    }

    const float cst = GAIN * rsqrtf((float)T);
#pragma unroll
    for (int rr = 0; rr < 2; rr++) {
        float s = 0.f;
#pragma unroll
        for (int nt = 0; nt < 8; nt++)
            s += oacc[nt][rr * 2] * oacc[nt][rr * 2] + oacc[nt][rr * 2 + 1] * oacc[nt][rr * 2 + 1];
        s += __shfl_xor_sync(~0u, s, 1);
        s += __shfl_xor_sync(~0u, s, 2);
        const int t = q0 + warp * 16 + g + rr * 8;
        const float n = cst * sqrtf(s);
        const float f = 8.0f * cst * g_mag[b * T + t] / (n + EPS);
        uint32_t* dp = g_att + ((size_t)b * T + t) * Dh + h * (HD / 2);
#pragma unroll
        for (int nt = 0; nt < 8; nt++)
            dp[nt * 4 + c] = h2(oacc[nt][rr * 2] * f, oacc[nt][rr * 2 + 1] * f);
    }
}

// ---------------------------------------------------------------------------
// Kernel 4: out-projection  y = att @ wn_out^T  (fp32 out)
// grid: (768/128, 8192/128), 256 threads.
// ---------------------------------------------------------------------------
__global__ void __launch_bounds__(256, 2) proj_mm(float* __restrict__ out) {
    extern __shared__ __align__(16) uint32_t dsm[];
    const int n0 = blockIdx.x * 128, m0 = blockIdx.y * 128;
    const int tid = threadIdx.x, lane = tid & 31, warp = tid >> 5;
    const int wm = warp >> 1, wn = warp & 1, g = lane >> 2, c = lane & 3;

    float acc[2][8][4] = {};
    gemm_core(g_att, g_wo, m0, n0, dsm, acc, tid);

#pragma unroll
    for (int mt = 0; mt < 2; mt++) {
#pragma unroll
        for (int rr = 0; rr < 2; rr++) {
            const int m = m0 + wm * 32 + mt * 16 + g + rr * 8;
            float* dp = out + (size_t)m * D + n0 + wn * 64;
#pragma unroll
            for (int nt = 0; nt < 8; nt++) {
                const int col = nt * 8 + 2 * c;
                *(float2*)&dp[col] = make_float2(acc[mt][nt][rr * 2],
                                                 acc[mt][nt][rr * 2 + 1]);
            }
        }
    }
}

// ---------------------------------------------------------------------------
extern "C" void kernel_launch(void* const* d_in, const int* in_sizes, int n_in,
                              void* d_out, int out_size) {
    const float* x     = (const float*)d_in[0];
    const float* qkv_w = (const float*)d_in[1];
    const float* out_w = (const float*)d_in[2];

    cudaFuncSetAttribute(qkv_mm, cudaFuncAttributeMaxDynamicSharedMemorySize, GEMM_SMEM);
    cudaFuncSetAttribute(proj_mm, cudaFuncAttributeMaxDynamicSharedMemorySize, GEMM_SMEM);
    cudaFuncSetAttribute(attn_mma, cudaFuncAttributeMaxDynamicSharedMemorySize, ATTN_SMEM);

    prep_kernel<<<(NQKV + D + BT) / 8, 256>>>(x, qkv_w, out_w);
    qkv_mm<<<dim3(NQKV / 128, BT / 128), 256, GEMM_SMEM>>>();
    attn_mma<<<dim3(T / 128, H, B), 256, ATTN_SMEM>>>();
    proj_mm<<<dim3(D / 128, BT / 128), 256, GEMM_SMEM>>>((float*)d_out);
}

// round 14
// speedup vs baseline: 1.0648x; 1.0056x over previous
#include <cuda_runtime.h>
#include <cuda_fp16.h>
#include <math.h>
#include <stdint.h>

// Problem constants
constexpr int B  = 4;
constexpr int T  = 2048;
constexpr int D  = 768;
constexpr int H  = 12;
constexpr int HD = 64;
constexpr int BT = B * T;          // 8192
constexpr int NQKV = 3 * D;        // 2304
constexpr float EPS  = 1e-4f;
constexpr float GAIN = 1.8402f;

constexpr int Dh   = D / 2;        // 384 uint32 (half2) per row

// GEMM: 128xBROWS tile, 256 threads (8 warps = 4m x 2n), 64-half chunks, 2 stages
constexpr int PADG = 36;           // 32 data + 4 pad u32
constexpr int KC2  = 32;           // chunk size in u32
constexpr int NC2  = Dh / KC2;     // 12 chunks
constexpr int A2_U32 = 128 * PADG;          // 4608

template <int BROWS> struct GemmCfg {
    static constexpr int BU32  = BROWS * PADG;
    static constexpr int STGU  = A2_U32 + BU32;
    static constexpr int SMEM  = 2 * STGU * 4;
    static constexpr int NT    = BROWS / 16;     // n-tiles per warp
};
constexpr int GEMM_SMEM_128 = GemmCfg<128>::SMEM;   // 73728
constexpr int GEMM_SMEM_96  = GemmCfg<96>::SMEM;    // 64512

// Attn: 128-key stages (two 64-key compute halves), 2-stage pipeline, 256 thr
constexpr int AK2   = 128 * 36;             // K tile: 128 keys x (32+4) u32
constexpr int AV2   = 64 * 68;              // Vt tile: 64 d x (64+4) u32
constexpr int ASTG2 = AK2 + AV2;            // 8960 u32 (35840 B)
constexpr int ATTN_SMEM = 2 * ASTG2 * 4;    // 71680 B
constexpr int NCT2  = T / 128;              // 16 stages

// Scratch (__device__ globals; fp16 storage packed as uint32 = half2)
__device__ uint32_t g_xh[BT * Dh];
__device__ uint32_t g_wq[NQKV * Dh];
__device__ uint32_t g_wo[D * Dh];
__device__ uint32_t g_Q[B * H * T * (HD / 2)];   // Q pre-scaled by 1/16
__device__ uint32_t g_K[B * H * T * (HD / 2)];
__device__ __half   g_Vt[(size_t)B * H * HD * T];   // V transposed: [b][h][d][t]
__device__ uint32_t g_att[BT * Dh];
__device__ float    g_mag[BT];

__device__ __forceinline__ uint32_t h2(float lo, float hi) {
    uint32_t u;  // first asm source -> upper 16 bits
    asm("cvt.rn.f16x2.f32 %0, %1, %2;" : "=r"(u) : "f"(hi), "f"(lo));
    return u;
}
__device__ __forceinline__ void mma16(float c[4], const uint32_t a[4], const uint32_t b[2]) {
    asm volatile(
        "mma.sync.aligned.m16n8k16.row.col.f32.f16.f16.f32 "
        "{%0,%1,%2,%3}, {%4,%5,%6,%7}, {%8,%9}, {%0,%1,%2,%3};"
        : "+f"(c[0]), "+f"(c[1]), "+f"(c[2]), "+f"(c[3])
        : "r"(a[0]), "r"(a[1]), "r"(a[2]), "r"(a[3]), "r"(b[0]), "r"(b[1]));
}
// f16-accumulate variant: C = {d0,d1} packed half2 (row g | row g+8, cols 2c..2c+1)
__device__ __forceinline__ void mma16h(uint32_t c[2], const uint32_t a[4], const uint32_t b[2]) {
    asm volatile(
        "mma.sync.aligned.m16n8k16.row.col.f16.f16.f16.f16 "
        "{%0,%1}, {%2,%3,%4,%5}, {%6,%7}, {%0,%1};"
        : "+r"(c[0]), "+r"(c[1])
        : "r"(a[0]), "r"(a[1]), "r"(a[2]), "r"(a[3]), "r"(b[0]), "r"(b[1]));
}
__device__ __forceinline__ uint32_t saddr(const void* p) {
    return (uint32_t)__cvta_generic_to_shared(p);
}
__device__ __forceinline__ void ldsm4(uint32_t* r, uint32_t a) {
    asm volatile("ldmatrix.sync.aligned.m8n8.x4.shared.b16 {%0,%1,%2,%3}, [%4];"
                 : "=r"(r[0]), "=r"(r[1]), "=r"(r[2]), "=r"(r[3]) : "r"(a));
}
__device__ __forceinline__ void cp16(uint32_t s, const void* g) {
    asm volatile("cp.async.cg.shared.global [%0], [%1], 16;" :: "r"(s), "l"(g));
}
__device__ __forceinline__ void cp_commit() {
    asm volatile("cp.async.commit_group;" ::: "memory");
}
template <int N>
__device__ __forceinline__ void cp_wait() {
    asm volatile("cp.async.wait_group %0;" :: "n"(N) : "memory");
}

// ---------------------------------------------------------------------------
// Kernel 1: warp-per-row. weight row-norm -> fp16; x -> fp16 + magnitude.
// ---------------------------------------------------------------------------
__global__ void __launch_bounds__(256) prep_kernel(const float* __restrict__ x,
                                                   const float* __restrict__ qkv_w,
                                                   const float* __restrict__ out_w) {
    const int row = blockIdx.x * 8 + (threadIdx.x >> 5);
    const int lane = threadIdx.x & 31;
    const float* src;
    uint32_t* dst;
    float* magdst = nullptr;
    bool donorm = true;
    if (row < NQKV) {
        src = qkv_w + (size_t)row * D;  dst = g_wq + (size_t)row * Dh;
    } else if (row < NQKV + D) {
        src = out_w + (size_t)(row - NQKV) * D;  dst = g_wo + (size_t)(row - NQKV) * Dh;
    } else {
        const int tr = row - (NQKV + D);
        src = x + (size_t)tr * D;  dst = g_xh + (size_t)tr * Dh;
        magdst = g_mag + tr;  donorm = false;
    }
    float4 v[6];
    float s = 0.f;
#pragma unroll
    for (int j = 0; j < 6; j++) {
        v[j] = ((const float4*)src)[lane + j * 32];
        s += v[j].x * v[j].x + v[j].y * v[j].y + v[j].z * v[j].z + v[j].w * v[j].w;
    }
#pragma unroll
    for (int o = 16; o > 0; o >>= 1) s += __shfl_xor_sync(0xffffffffu, s, o);
    if (donorm) {
        const float inv = 1.0f / (sqrtf(s) + EPS);
#pragma unroll
        for (int j = 0; j < 6; j++) {
            dst[2 * (lane + j * 32)]     = h2(v[j].x * inv, v[j].y * inv);
            dst[2 * (lane + j * 32) + 1] = h2(v[j].z * inv, v[j].w * inv);
        }
    } else {
#pragma unroll
        for (int j = 0; j < 6; j++) {
            dst[2 * (lane + j * 32)]     = h2(v[j].x, v[j].y);
            dst[2 * (lane + j * 32) + 1] = h2(v[j].z, v[j].w);
        }
        if (lane == 0) magdst[0] = sqrtf(s) * (1.0f / sqrtf((float)D));
    }
}

// ---------------------------------------------------------------------------
// fp16 GEMM core (templated on B-tile rows): C[128 x BROWS], 256 threads,
// 8 warps (4m x 2n), warp tile 32 x BROWS/2. 2-stage cp.async, 1 barrier/chunk.
// ---------------------------------------------------------------------------
template <int BROWS>
__device__ __forceinline__ void gemm_core(const uint32_t* __restrict__ A,
                                          const uint32_t* __restrict__ W,
                                          int m0, int n0, uint32_t* sm,
                                          float (&acc)[2][GemmCfg<BROWS>::NT][4], int tid) {
    using C = GemmCfg<BROWS>;
    const int lane = tid & 31, warp = tid >> 5;
    const int wm = warp >> 1, wn = warp & 1;
    const uint32_t* Ab = A + (size_t)m0 * Dh;
    const uint32_t* Wb = W + (size_t)n0 * Dh;
    const uint32_t sb = saddr(sm);

    const uint32_t a_off = ((wm * 32 + (lane & 15)) * PADG + (lane >> 4) * 4) << 2;
    const uint32_t b_off = (A2_U32 + (wn * (BROWS / 2) + ((lane >> 4) & 1) * 8 + (lane & 7)) * PADG +
                            ((lane >> 3) & 1) * 4) << 2;

    auto stage = [&](int s, int c) {
        const uint32_t base = sb + (uint32_t)(s * C::STGU) * 4;
        const int k0 = c * KC2;
#pragma unroll
        for (int j = 0; j < 4; j++) {            // A: 128 rows x 8 segs of 16B
            const int idx = tid + j * 256;
            const int row = idx >> 3, seg = idx & 7;
            cp16(base + ((row * PADG + seg * 4) << 2), Ab + (size_t)row * Dh + k0 + seg * 4);
        }
#pragma unroll
        for (int j = 0; j < BROWS / 32; j++) {   // B: BROWS rows x 8 segs of 16B
            const int idx = tid + j * 256;
            const int row = idx >> 3, seg = idx & 7;
            cp16(base + ((A2_U32 + row * PADG + seg * 4) << 2), Wb + (size_t)row * Dh + k0 + seg * 4);
        }
        cp_commit();
    };

    stage(0, 0);
    for (int k = 0; k < NC2; k++) {
        cp_wait<0>();
        __syncthreads();
        if (k + 1 < NC2) stage((k + 1) & 1, k + 1);   // overlaps compute below
        const uint32_t base = sb + (uint32_t)((k & 1) * C::STGU) * 4;
#pragma unroll
        for (int ks = 0; ks < 4; ks++) {
            const uint32_t kk4 = (ks * 8) << 2;
            uint32_t af[2][4], bq[C::NT / 2][4];
            ldsm4(af[0], base + a_off + kk4);
            ldsm4(af[1], base + a_off + ((16 * PADG) << 2) + kk4);
#pragma unroll
            for (int np = 0; np < C::NT / 2; np++)
                ldsm4(bq[np], base + b_off + ((np * 16 * PADG) << 2) + kk4);
#pragma unroll
            for (int mt = 0; mt < 2; mt++)
#pragma unroll
                for (int np = 0; np < C::NT / 2; np++) {
                    mma16(acc[mt][2 * np],     af[mt], bq[np]);
                    mma16(acc[mt][2 * np + 1], af[mt], bq[np] + 2);
                }
        }
    }
}

// ---------------------------------------------------------------------------
// Kernel 2: qkv GEMM (128x128) + warp-local per-head q/k RMS-normalize.
// Q stored PRE-SCALED by 1/16. V transposed via smem for coalesced g_Vt.
// grid: (2304/128, 8192/128), 256 threads.
// ---------------------------------------------------------------------------
__global__ void __launch_bounds__(256, 2) qkv_mm() {
    extern __shared__ __align__(16) uint32_t dsm[];
    const int n0 = blockIdx.x * 128, m0 = blockIdx.y * 128;
    const int tid = threadIdx.x, lane = tid & 31, warp = tid >> 5;
    const int wm = warp >> 1, wn = warp & 1, g = lane >> 2, c = lane & 3;

    float acc[2][8][4] = {};
    gemm_core<128>(g_xh, g_wq, m0, n0, dsm, acc, tid);

    const int which = n0 / D;                      // 0=q 1=k 2=v
    const int headbase = (n0 % D) >> 6;
    const int b = m0 / T;

    if (which < 2) {
        const int head = headbase + wn;
        uint32_t* dstb = (which == 0) ? g_Q : g_K;
        const float nrm = (which == 0) ? 0.5f : 8.0f;   // q: 8/16 folded
#pragma unroll
        for (int mt = 0; mt < 2; mt++) {
            float s0 = 0.f, s1 = 0.f;
#pragma unroll
            for (int nt = 0; nt < 8; nt++) {
                s0 += acc[mt][nt][0] * acc[mt][nt][0] + acc[mt][nt][1] * acc[mt][nt][1];
                s1 += acc[mt][nt][2] * acc[mt][nt][2] + acc[mt][nt][3] * acc[mt][nt][3];
            }
            s0 += __shfl_xor_sync(~0u, s0, 1); s0 += __shfl_xor_sync(~0u, s0, 2);
            s1 += __shfl_xor_sync(~0u, s1, 1); s1 += __shfl_xor_sync(~0u, s1, 2);
            const float sc[2] = {nrm / (sqrtf(s0) + EPS), nrm / (sqrtf(s1) + EPS)};
#pragma unroll
            for (int rr = 0; rr < 2; rr++) {
                const int t = (m0 + wm * 32 + mt * 16 + g + rr * 8) & (T - 1);
                uint32_t* dp = dstb + (((size_t)(b * H + head)) * T + t) * (HD / 2);
#pragma unroll
                for (int nt = 0; nt < 8; nt++)
                    dp[nt * 4 + c] = h2(acc[mt][nt][rr * 2] * sc[rr],
                                        acc[mt][nt][rr * 2 + 1] * sc[rr]);
            }
        }
    } else {
        // V: transpose via smem, then coalesced row writes to g_Vt.
        __syncthreads();                           // last chunk's ldsm reads done
        __half* Vsm = (__half*)dsm;                // [128 d][136 halfs]
#pragma unroll
        for (int mt = 0; mt < 2; mt++)
#pragma unroll
            for (int rr = 0; rr < 2; rr++) {
                const int tl = wm * 32 + mt * 16 + g + rr * 8;
#pragma unroll
                for (int nt = 0; nt < 8; nt++) {
                    const int d0 = wn * 64 + nt * 8 + 2 * c;
                    Vsm[d0 * 136 + tl]       = __float2half(acc[mt][nt][rr * 2]);
                    Vsm[(d0 + 1) * 136 + tl] = __float2half(acc[mt][nt][rr * 2 + 1]);
                }
            }
        __syncthreads();
        const int col = tid & 127;                 // d_local (2 heads x 64)
        const int hf = tid >> 7;                   // t half
        const int head = headbase + (col >> 6);
        const int dd = col & 63;
        const int t0 = (m0 & (T - 1)) + hf * 64;
        const uint4* srcv = (const uint4*)(Vsm + col * 136 + hf * 64);
        uint4* dstv = (uint4*)(g_Vt + ((size_t)(b * H + head) * HD + dd) * T + t0);
#pragma unroll
        for (int j = 0; j < 8; j++) dstv[j] = srcv[j];
    }
}

// ---------------------------------------------------------------------------
// Kernel 3: fused sigmoid attention. S-mma with f16 ACCUMULATE (2x rate);
// f16 C-frags ARE the PV A-frags (no cvt). Q pre-scaled by 1/16.
// 128-key 2-stage pipeline. grid: (T/128, H, B), 256 thr.
// ---------------------------------------------------------------------------
__global__ void __launch_bounds__(256) attn_mma() {
    extern __shared__ __align__(16) uint32_t dsm[];
    const int tid = threadIdx.x, lane = tid & 31, warp = tid >> 5;
    const int g = lane >> 2, c = lane & 3;
    const int q0 = blockIdx.x * 128;
    const int h = blockIdx.y, b = blockIdx.z;
    const size_t bh = ((size_t)(b * H + h)) * T;

    uint32_t qf[4][4];
    {
        const uint32_t* Qg = g_Q + (bh + q0 + warp * 16) * (HD / 2);
#pragma unroll
        for (int ks = 0; ks < 4; ks++) {
            qf[ks][0] = Qg[(size_t)g * 32 + ks * 8 + c];
            qf[ks][1] = Qg[(size_t)(g + 8) * 32 + ks * 8 + c];
            qf[ks][2] = Qg[(size_t)g * 32 + ks * 8 + c + 4];
            qf[ks][3] = Qg[(size_t)(g + 8) * 32 + ks * 8 + c + 4];
        }
    }

    const uint32_t sb = saddr(dsm);
    const uint32_t krow = ((lane >> 4) & 1) * 8 + (lane & 7);
    const uint32_t kcol = ((lane >> 3) & 1) * 4;
    const uint32_t kb_off = (krow * 36 + kcol) << 2;
    const uint32_t vb_off = (AK2 + krow * 68 + kcol) << 2;

    const uint32_t* Kg0  = g_K + bh * (HD / 2);
    const uint32_t* Vtg0 = (const uint32_t*)(g_Vt + bh * HD);  // rows of T/2 uint32

    auto stage_kv = [&](int s, int i) {
        const uint32_t base = sb + (uint32_t)(s * ASTG2) * 4;
#pragma unroll
        for (int j = 0; j < 4; j++) {              // K: 128 rows x 8 segs
            const int idx = tid + j * 256;
            const int row = idx >> 3, seg = idx & 7;
            cp16(base + ((row * 36 + seg * 4) << 2),
                 Kg0 + (size_t)(i * 128 + row) * 32 + seg * 4);
        }
#pragma unroll
        for (int j = 0; j < 4; j++) {              // Vt: 64 rows x 16 segs
            const int idx = tid + j * 256;
            const int row = idx >> 4, seg = idx & 15;
            cp16(base + ((AK2 + row * 68 + seg * 4) << 2),
                 Vtg0 + (size_t)row * (T / 2) + i * 64 + seg * 4);
        }
        cp_commit();
    };

    float oacc[8][4] = {};

    stage_kv(0, 0);
    for (int i = 0; i < NCT2; i++) {
        cp_wait<0>();
        __syncthreads();
        if (i + 1 < NCT2) stage_kv((i + 1) & 1, i + 1);
        const uint32_t base = sb + (uint32_t)((i & 1) * ASTG2) * 4;

#pragma unroll
        for (int hh = 0; hh < 2; hh++) {
            // S = (Q/16) K^T in f16 accum: sacc[nt] = {d0,d1} packed half2
            uint32_t sacc[8][2] = {};
#pragma unroll
            for (int ks = 0; ks < 4; ks++) {
                uint32_t bq[4][4];
#pragma unroll
                for (int np = 0; np < 4; np++)
                    ldsm4(bq[np], base + kb_off + (((hh * 64 + np * 16) * 36 + ks * 8) << 2));
#pragma unroll
                for (int np = 0; np < 4; np++) {
                    mma16h(sacc[2 * np],     qf[ks], bq[np]);
                    mma16h(sacc[2 * np + 1], qf[ks], bq[np] + 2);
                }
            }
            // O += sigmoid V : f16 C-frags are the A-frags; tanh.f16x2 in place
#pragma unroll
            for (int kt = 0; kt < 4; kt++) {
                uint32_t af[4] = {sacc[2 * kt][0], sacc[2 * kt][1],
                                  sacc[2 * kt + 1][0], sacc[2 * kt + 1][1]};
#pragma unroll
                for (int j = 0; j < 4; j++) {
                    asm("tanh.approx.f16x2 %0, %0;" : "+r"(af[j]));
                    asm("fma.rn.f16x2 %0, %0, %1, %1;" : "+r"(af[j]) : "r"(0x38003800u));
                }
                uint32_t bq[4][4];
#pragma unroll
                for (int np = 0; np < 4; np++)
                    ldsm4(bq[np], base + vb_off + ((np * 16 * 68 + hh * 32 + kt * 8) << 2));
#pragma unroll
                for (int np = 0; np < 4; np++) {
                    mma16(oacc[2 * np],     af, bq[np]);
                    mma16(oacc[2 * np + 1], af, bq[np] + 2);
                }
            }
        }
    }

    const float cst = GAIN * rsqrtf((float)T);
#pragma unroll
    for (int rr = 0; rr < 2; rr++) {
        float s = 0.f;
#pragma unroll
        for (int nt = 0; nt < 8; nt++)
            s += oacc[nt][rr * 2] * oacc[nt][rr * 2] + oacc[nt][rr * 2 + 1] * oacc[nt][rr * 2 + 1];
        s += __shfl_xor_sync(~0u, s, 1);
        s += __shfl_xor_sync(~0u, s, 2);
        const int t = q0 + warp * 16 + g + rr * 8;
        const float n = cst * sqrtf(s);
        const float f = 8.0f * cst * g_mag[b * T + t] / (n + EPS);
        uint32_t* dp = g_att + ((size_t)b * T + t) * Dh + h * (HD / 2);
#pragma unroll
        for (int nt = 0; nt < 8; nt++)
            dp[nt * 4 + c] = h2(oacc[nt][rr * 2] * f, oacc[nt][rr * 2 + 1] * f);
    }
}

// ---------------------------------------------------------------------------
// Kernel 4: out-projection (128x96 tiles for wave packing)  y = att @ wn_out^T
// grid: (768/96, 8192/128), 256 threads.
// ---------------------------------------------------------------------------
__global__ void __launch_bounds__(256, 2) proj_mm(float* __restrict__ out) {
    extern __shared__ __align__(16) uint32_t dsm[];
    const int n0 = blockIdx.x * 96, m0 = blockIdx.y * 128;
    const int tid = threadIdx.x, lane = tid & 31, warp = tid >> 5;
    const int wm = warp >> 1, wn = warp & 1, g = lane >> 2, c = lane & 3;

    float acc[2][6][4] = {};
    gemm_core<96>(g_att, g_wo, m0, n0, dsm, acc, tid);

#pragma unroll
    for (int mt = 0; mt < 2; mt++) {
#pragma unroll
        for (int rr = 0; rr < 2; rr++) {
            const int m = m0 + wm * 32 + mt * 16 + g + rr * 8;
            float* dp = out + (size_t)m * D + n0 + wn * 48;
#pragma unroll
            for (int nt = 0; nt < 6; nt++) {
                const int col = nt * 8 + 2 * c;
                *(float2*)&dp[col] = make_float2(acc[mt][nt][rr * 2],
                                                 acc[mt][nt][rr * 2 + 1]);
            }
        }
    }
}

// ---------------------------------------------------------------------------
extern "C" void kernel_launch(void* const* d_in, const int* in_sizes, int n_in,
                              void* d_out, int out_size) {
    const float* x     = (const float*)d_in[0];
    const float* qkv_w = (const float*)d_in[1];
    const float* out_w = (const float*)d_in[2];

    cudaFuncSetAttribute(qkv_mm, cudaFuncAttributeMaxDynamicSharedMemorySize, GEMM_SMEM_128);
    cudaFuncSetAttribute(proj_mm, cudaFuncAttributeMaxDynamicSharedMemorySize, GEMM_SMEM_96);
    cudaFuncSetAttribute(attn_mma, cudaFuncAttributeMaxDynamicSharedMemorySize, ATTN_SMEM);

    prep_kernel<<<(NQKV + D + BT) / 8, 256>>>(x, qkv_w, out_w);
    qkv_mm<<<dim3(NQKV / 128, BT / 128), 256, GEMM_SMEM_128>>>();
    attn_mma<<<dim3(T / 128, H, B), 256, ATTN_SMEM>>>();
    proj_mm<<<dim3(D / 96, BT / 128), 256, GEMM_SMEM_96>>>((float*)d_out);
}

// round 15
// speedup vs baseline: 1.1080x; 1.0406x over previous
#include <cuda_runtime.h>
#include <cuda_fp16.h>
#include <math.h>
#include <stdint.h>

// Problem constants
constexpr int B  = 4;
constexpr int T  = 2048;
constexpr int D  = 768;
constexpr int H  = 12;
constexpr int HD = 64;
constexpr int BT = B * T;          // 8192
constexpr int NQKV = 3 * D;        // 2304
constexpr float EPS  = 1e-4f;
constexpr float GAIN = 1.8402f;

constexpr int Dh   = D / 2;        // 384 uint32 (half2) per row

// GEMM: 128x128 tile, 256 threads (8 warps = 4m x 2n), 64-half chunks, 2 stages
constexpr int PADG = 36;           // 32 data + 4 pad u32
constexpr int KC2  = 32;           // chunk size in u32
constexpr int NC2  = Dh / KC2;     // 12 chunks
constexpr int A2_U32   = 128 * PADG;        // 4608
constexpr int STG2_U32 = 2 * A2_U32;        // 9216 (36864 B)
constexpr int GEMM_SMEM = 2 * STG2_U32 * 4; // 73728 B

// Attn: q-tile 256 (512 threads, 16 warps x 16 q-rows), 128-key 2-stage pipeline
constexpr int AK2   = 128 * 36;             // K tile: 128 keys x (32+4) u32
constexpr int AV2   = 64 * 68;              // Vt tile: 64 d x (64+4) u32
constexpr int ASTG2 = AK2 + AV2;            // 8960 u32 (35840 B)
constexpr int ATTN_SMEM = 2 * ASTG2 * 4;    // 71680 B
constexpr int NCT2  = T / 128;              // 16 stages

// Scratch (__device__ globals; fp16 storage packed as uint32 = half2)
__device__ uint32_t g_xh[BT * Dh];
__device__ uint32_t g_wq[NQKV * Dh];
__device__ uint32_t g_wo[D * Dh];
__device__ uint32_t g_Q[B * H * T * (HD / 2)];   // Q pre-scaled by 1/16
__device__ uint32_t g_K[B * H * T * (HD / 2)];
__device__ __half   g_Vt[(size_t)B * H * HD * T];   // V transposed: [b][h][d][t]
__device__ uint32_t g_att[BT * Dh];
__device__ float    g_mag[BT];

__device__ __forceinline__ uint32_t h2(float lo, float hi) {
    uint32_t u;  // first asm source -> upper 16 bits
    asm("cvt.rn.f16x2.f32 %0, %1, %2;" : "=r"(u) : "f"(hi), "f"(lo));
    return u;
}
__device__ __forceinline__ void mma16(float c[4], const uint32_t a[4], const uint32_t b[2]) {
    asm volatile(
        "mma.sync.aligned.m16n8k16.row.col.f32.f16.f16.f32 "
        "{%0,%1,%2,%3}, {%4,%5,%6,%7}, {%8,%9}, {%0,%1,%2,%3};"
        : "+f"(c[0]), "+f"(c[1]), "+f"(c[2]), "+f"(c[3])
        : "r"(a[0]), "r"(a[1]), "r"(a[2]), "r"(a[3]), "r"(b[0]), "r"(b[1]));
}
// f16-accumulate variant: C = {d0,d1} packed half2 (row g | row g+8, cols 2c..2c+1)
__device__ __forceinline__ void mma16h(uint32_t c[2], const uint32_t a[4], const uint32_t b[2]) {
    asm volatile(
        "mma.sync.aligned.m16n8k16.row.col.f16.f16.f16.f16 "
        "{%0,%1}, {%2,%3,%4,%5}, {%6,%7}, {%0,%1};"
        : "+r"(c[0]), "+r"(c[1])
        : "r"(a[0]), "r"(a[1]), "r"(a[2]), "r"(a[3]), "r"(b[0]), "r"(b[1]));
}
__device__ __forceinline__ uint32_t saddr(const void* p) {
    return (uint32_t)__cvta_generic_to_shared(p);
}
__device__ __forceinline__ void ldsm4(uint32_t* r, uint32_t a) {
    asm volatile("ldmatrix.sync.aligned.m8n8.x4.shared.b16 {%0,%1,%2,%3}, [%4];"
                 : "=r"(r[0]), "=r"(r[1]), "=r"(r[2]), "=r"(r[3]) : "r"(a));
}
__device__ __forceinline__ void cp16(uint32_t s, const void* g) {
    asm volatile("cp.async.cg.shared.global [%0], [%1], 16;" :: "r"(s), "l"(g));
}
__device__ __forceinline__ void cp_commit() {
    asm volatile("cp.async.commit_group;" ::: "memory");
}
template <int N>
__device__ __forceinline__ void cp_wait() {
    asm volatile("cp.async.wait_group %0;" :: "n"(N) : "memory");
}

// ---------------------------------------------------------------------------
// Kernel 1: warp-per-row. weight row-norm -> fp16; x -> fp16 + magnitude.
// ---------------------------------------------------------------------------
__global__ void __launch_bounds__(256) prep_kernel(const float* __restrict__ x,
                                                   const float* __restrict__ qkv_w,
                                                   const float* __restrict__ out_w) {
    const int row = blockIdx.x * 8 + (threadIdx.x >> 5);
    const int lane = threadIdx.x & 31;
    const float* src;
    uint32_t* dst;
    float* magdst = nullptr;
    bool donorm = true;
    if (row < NQKV) {
        src = qkv_w + (size_t)row * D;  dst = g_wq + (size_t)row * Dh;
    } else if (row < NQKV + D) {
        src = out_w + (size_t)(row - NQKV) * D;  dst = g_wo + (size_t)(row - NQKV) * Dh;
    } else {
        const int tr = row - (NQKV + D);
        src = x + (size_t)tr * D;  dst = g_xh + (size_t)tr * Dh;
        magdst = g_mag + tr;  donorm = false;
    }
    float4 v[6];
    float s = 0.f;
#pragma unroll
    for (int j = 0; j < 6; j++) {
        v[j] = ((const float4*)src)[lane + j * 32];
        s += v[j].x * v[j].x + v[j].y * v[j].y + v[j].z * v[j].z + v[j].w * v[j].w;
    }
#pragma unroll
    for (int o = 16; o > 0; o >>= 1) s += __shfl_xor_sync(0xffffffffu, s, o);
    if (donorm) {
        const float inv = 1.0f / (sqrtf(s) + EPS);
#pragma unroll
        for (int j = 0; j < 6; j++) {
            dst[2 * (lane + j * 32)]     = h2(v[j].x * inv, v[j].y * inv);
            dst[2 * (lane + j * 32) + 1] = h2(v[j].z * inv, v[j].w * inv);
        }
    } else {
#pragma unroll
        for (int j = 0; j < 6; j++) {
            dst[2 * (lane + j * 32)]     = h2(v[j].x, v[j].y);
            dst[2 * (lane + j * 32) + 1] = h2(v[j].z, v[j].w);
        }
        if (lane == 0) magdst[0] = sqrtf(s) * (1.0f / sqrtf((float)D));
    }
}

// ---------------------------------------------------------------------------
// fp16 GEMM core: 128x128 tile, 64-half chunks, 2-stage cp.async pipeline.
// 8 warps (4m x 2n), warp tile 32x64. One __syncthreads per chunk (12 total).
// ---------------------------------------------------------------------------
__device__ __forceinline__ void gemm_core(const uint32_t* __restrict__ A,
                                          const uint32_t* __restrict__ W,
                                          int m0, int n0, uint32_t* sm,
                                          float (&acc)[2][8][4], int tid) {
    const int lane = tid & 31, warp = tid >> 5;
    const int wm = warp >> 1, wn = warp & 1;
    const uint32_t* Ab = A + (size_t)m0 * Dh;
    const uint32_t* Wb = W + (size_t)n0 * Dh;
    const uint32_t sb = saddr(sm);

    const uint32_t a_off = ((wm * 32 + (lane & 15)) * PADG + (lane >> 4) * 4) << 2;
    const uint32_t b_off = (A2_U32 + (wn * 64 + ((lane >> 4) & 1) * 8 + (lane & 7)) * PADG +
                            ((lane >> 3) & 1) * 4) << 2;

    auto stage = [&](int s, int c) {
        const uint32_t base = sb + (uint32_t)(s * STG2_U32) * 4;
        const int k0 = c * KC2;
#pragma unroll
        for (int j = 0; j < 4; j++) {            // A: 128 rows x 8 segs of 16B
            const int idx = tid + j * 256;
            const int row = idx >> 3, seg = idx & 7;
            cp16(base + ((row * PADG + seg * 4) << 2), Ab + (size_t)row * Dh + k0 + seg * 4);
        }
#pragma unroll
        for (int j = 0; j < 4; j++) {            // B: 128 rows x 8 segs of 16B
            const int idx = tid + j * 256;
            const int row = idx >> 3, seg = idx & 7;
            cp16(base + ((A2_U32 + row * PADG + seg * 4) << 2), Wb + (size_t)row * Dh + k0 + seg * 4);
        }
        cp_commit();
    };

    stage(0, 0);
    for (int k = 0; k < NC2; k++) {
        cp_wait<0>();
        __syncthreads();
        if (k + 1 < NC2) stage((k + 1) & 1, k + 1);   // overlaps compute below
        const uint32_t base = sb + (uint32_t)((k & 1) * STG2_U32) * 4;
#pragma unroll
        for (int ks = 0; ks < 4; ks++) {
            const uint32_t kk4 = (ks * 8) << 2;
            uint32_t af[2][4], bq[4][4];
            ldsm4(af[0], base + a_off + kk4);
            ldsm4(af[1], base + a_off + ((16 * PADG) << 2) + kk4);
#pragma unroll
            for (int np = 0; np < 4; np++)
                ldsm4(bq[np], base + b_off + ((np * 16 * PADG) << 2) + kk4);
#pragma unroll
            for (int mt = 0; mt < 2; mt++)
#pragma unroll
                for (int np = 0; np < 4; np++) {
                    mma16(acc[mt][2 * np],     af[mt], bq[np]);
                    mma16(acc[mt][2 * np + 1], af[mt], bq[np] + 2);
                }
        }
    }
}

// ---------------------------------------------------------------------------
// Kernel 2: qkv GEMM + warp-local per-head q/k RMS-normalize + scatter.
// Q stored PRE-SCALED by 1/16. V transposed via smem for coalesced g_Vt.
// grid: (2304/128, 8192/128), 256 threads.
// ---------------------------------------------------------------------------
__global__ void __launch_bounds__(256, 2) qkv_mm() {
    extern __shared__ __align__(16) uint32_t dsm[];
    const int n0 = blockIdx.x * 128, m0 = blockIdx.y * 128;
    const int tid = threadIdx.x, lane = tid & 31, warp = tid >> 5;
    const int wm = warp >> 1, wn = warp & 1, g = lane >> 2, c = lane & 3;

    float acc[2][8][4] = {};
    gemm_core(g_xh, g_wq, m0, n0, dsm, acc, tid);

    const int which = n0 / D;                      // 0=q 1=k 2=v
    const int headbase = (n0 % D) >> 6;
    const int b = m0 / T;

    if (which < 2) {
        const int head = headbase + wn;
        uint32_t* dstb = (which == 0) ? g_Q : g_K;
        const float nrm = (which == 0) ? 0.5f : 8.0f;   // q: 8/16 folded
#pragma unroll
        for (int mt = 0; mt < 2; mt++) {
            float s0 = 0.f, s1 = 0.f;
#pragma unroll
            for (int nt = 0; nt < 8; nt++) {
                s0 += acc[mt][nt][0] * acc[mt][nt][0] + acc[mt][nt][1] * acc[mt][nt][1];
                s1 += acc[mt][nt][2] * acc[mt][nt][2] + acc[mt][nt][3] * acc[mt][nt][3];
            }
            s0 += __shfl_xor_sync(~0u, s0, 1); s0 += __shfl_xor_sync(~0u, s0, 2);
            s1 += __shfl_xor_sync(~0u, s1, 1); s1 += __shfl_xor_sync(~0u, s1, 2);
            const float sc[2] = {nrm / (sqrtf(s0) + EPS), nrm / (sqrtf(s1) + EPS)};
#pragma unroll
            for (int rr = 0; rr < 2; rr++) {
                const int t = (m0 + wm * 32 + mt * 16 + g + rr * 8) & (T - 1);
                uint32_t* dp = dstb + (((size_t)(b * H + head)) * T + t) * (HD / 2);
#pragma unroll
                for (int nt = 0; nt < 8; nt++)
                    dp[nt * 4 + c] = h2(acc[mt][nt][rr * 2] * sc[rr],
                                        acc[mt][nt][rr * 2 + 1] * sc[rr]);
            }
        }
    } else {
        // V: transpose via smem, then coalesced row writes to g_Vt.
        __syncthreads();                           // last chunk's ldsm reads done
        __half* Vsm = (__half*)dsm;                // [128 d][136 halfs]
#pragma unroll
        for (int mt = 0; mt < 2; mt++)
#pragma unroll
            for (int rr = 0; rr < 2; rr++) {
                const int tl = wm * 32 + mt * 16 + g + rr * 8;
#pragma unroll
                for (int nt = 0; nt < 8; nt++) {
                    const int d0 = wn * 64 + nt * 8 + 2 * c;
                    Vsm[d0 * 136 + tl]       = __float2half(acc[mt][nt][rr * 2]);
                    Vsm[(d0 + 1) * 136 + tl] = __float2half(acc[mt][nt][rr * 2 + 1]);
                }
            }
        __syncthreads();
        const int col = tid & 127;                 // d_local (2 heads x 64)
        const int hf = tid >> 7;                   // t half
        const int head = headbase + (col >> 6);
        const int dd = col & 63;
        const int t0 = (m0 & (T - 1)) + hf * 64;
        const uint4* srcv = (const uint4*)(Vsm + col * 136 + hf * 64);
        uint4* dstv = (uint4*)(g_Vt + ((size_t)(b * H + head) * HD + dd) * T + t0);
#pragma unroll
        for (int j = 0; j < 8; j++) dstv[j] = srcv[j];
    }
}

// ---------------------------------------------------------------------------
// Kernel 3: fused sigmoid attention. q-tile 256, 512 threads (16 warps x 16
// q-rows) -> HALVES K/V L2 traffic vs 128-q-tile at identical warps/SM.
// S-mma f16-accum; f16 C-frags ARE the PV A-frags. Q pre-scaled by 1/16.
// grid: (T/256, H, B). 71680 B dynamic smem.
// ---------------------------------------------------------------------------
__global__ void __launch_bounds__(512, 1) attn_mma() {
    extern __shared__ __align__(16) uint32_t dsm[];
    const int tid = threadIdx.x, lane = tid & 31, warp = tid >> 5;
    const int g = lane >> 2, c = lane & 3;
    const int q0 = blockIdx.x * 256;
    const int h = blockIdx.y, b = blockIdx.z;
    const size_t bh = ((size_t)(b * H + h)) * T;

    uint32_t qf[4][4];
    {
        const uint32_t* Qg = g_Q + (bh + q0 + warp * 16) * (HD / 2);
#pragma unroll
        for (int ks = 0; ks < 4; ks++) {
            qf[ks][0] = Qg[(size_t)g * 32 + ks * 8 + c];
            qf[ks][1] = Qg[(size_t)(g + 8) * 32 + ks * 8 + c];
            qf[ks][2] = Qg[(size_t)g * 32 + ks * 8 + c + 4];
            qf[ks][3] = Qg[(size_t)(g + 8) * 32 + ks * 8 + c + 4];
        }
    }

    const uint32_t sb = saddr(dsm);
    const uint32_t krow = ((lane >> 4) & 1) * 8 + (lane & 7);
    const uint32_t kcol = ((lane >> 3) & 1) * 4;
    const uint32_t kb_off = (krow * 36 + kcol) << 2;
    const uint32_t vb_off = (AK2 + krow * 68 + kcol) << 2;

    const uint32_t* Kg0  = g_K + bh * (HD / 2);
    const uint32_t* Vtg0 = (const uint32_t*)(g_Vt + bh * HD);  // rows of T/2 uint32

    auto stage_kv = [&](int s, int i) {
        const uint32_t base = sb + (uint32_t)(s * ASTG2) * 4;
#pragma unroll
        for (int j = 0; j < 2; j++) {              // K: 128 rows x 8 segs
            const int idx = tid + j * 512;
            const int row = idx >> 3, seg = idx & 7;
            cp16(base + ((row * 36 + seg * 4) << 2),
                 Kg0 + (size_t)(i * 128 + row) * 32 + seg * 4);
        }
#pragma unroll
        for (int j = 0; j < 2; j++) {              // Vt: 64 rows x 16 segs
            const int idx = tid + j * 512;
            const int row = idx >> 4, seg = idx & 15;
            cp16(base + ((AK2 + row * 68 + seg * 4) << 2),
                 Vtg0 + (size_t)row * (T / 2) + i * 64 + seg * 4);
        }
        cp_commit();
    };

    float oacc[8][4] = {};

    stage_kv(0, 0);
    for (int i = 0; i < NCT2; i++) {
        cp_wait<0>();
        __syncthreads();
        if (i + 1 < NCT2) stage_kv((i + 1) & 1, i + 1);
        const uint32_t base = sb + (uint32_t)((i & 1) * ASTG2) * 4;

#pragma unroll
        for (int hh = 0; hh < 2; hh++) {
            // S = (Q/16) K^T in f16 accum: sacc[nt] = {d0,d1} packed half2
            uint32_t sacc[8][2] = {};
#pragma unroll
            for (int ks = 0; ks < 4; ks++) {
                uint32_t bq[4][4];
#pragma unroll
                for (int np = 0; np < 4; np++)
                    ldsm4(bq[np], base + kb_off + (((hh * 64 + np * 16) * 36 + ks * 8) << 2));
#pragma unroll
                for (int np = 0; np < 4; np++) {
                    mma16h(sacc[2 * np],     qf[ks], bq[np]);
                    mma16h(sacc[2 * np + 1], qf[ks], bq[np] + 2);
                }
            }
            // O += sigmoid V : f16 C-frags are the A-frags; tanh.f16x2 in place
#pragma unroll
            for (int kt = 0; kt < 4; kt++) {
                uint32_t af[4] = {sacc[2 * kt][0], sacc[2 * kt][1],
                                  sacc[2 * kt + 1][0], sacc[2 * kt + 1][1]};
#pragma unroll
                for (int j = 0; j < 4; j++) {
                    asm("tanh.approx.f16x2 %0, %0;" : "+r"(af[j]));
                    asm("fma.rn.f16x2 %0, %0, %1, %1;" : "+r"(af[j]) : "r"(0x38003800u));
                }
                uint32_t bq[4][4];
#pragma unroll
                for (int np = 0; np < 4; np++)
                    ldsm4(bq[np], base + vb_off + ((np * 16 * 68 + hh * 32 + kt * 8) << 2));
#pragma unroll
                for (int np = 0; np < 4; np++) {
                    mma16(oacc[2 * np],     af, bq[np]);
                    mma16(oacc[2 * np + 1], af, bq[np] + 2);
                }
            }
        }
    }

    const float cst = GAIN * rsqrtf((float)T);
#pragma unroll
    for (int rr = 0; rr < 2; rr++) {
        float s = 0.f;
#pragma unroll
        for (int nt = 0; nt < 8; nt++)
            s += oacc[nt][rr * 2] * oacc[nt][rr * 2] + oacc[nt][rr * 2 + 1] * oacc[nt][rr * 2 + 1];
        s += __shfl_xor_sync(~0u, s, 1);
        s += __shfl_xor_sync(~0u, s, 2);
        const int t = q0 + warp * 16 + g + rr * 8;
        const float n = cst * sqrtf(s);
        const float f = 8.0f * cst * g_mag[b * T + t] / (n + EPS);
        uint32_t* dp = g_att + ((size_t)b * T + t) * Dh + h * (HD / 2);
#pragma unroll
        for (int nt = 0; nt < 8; nt++)
            dp[nt * 4 + c] = h2(oacc[nt][rr * 2] * f, oacc[nt][rr * 2 + 1] * f);
    }
}

// ---------------------------------------------------------------------------
// Kernel 4: out-projection  y = att @ wn_out^T  (fp32 out)
// grid: (768/128, 8192/128), 256 threads.
// ---------------------------------------------------------------------------
__global__ void __launch_bounds__(256, 2) proj_mm(float* __restrict__ out) {
    extern __shared__ __align__(16) uint32_t dsm[];
    const int n0 = blockIdx.x * 128, m0 = blockIdx.y * 128;
    const int tid = threadIdx.x, lane = tid & 31, warp = tid >> 5;
    const int wm = warp >> 1, wn = warp & 1, g = lane >> 2, c = lane & 3;

    float acc[2][8][4] = {};
    gemm_core(g_att, g_wo, m0, n0, dsm, acc, tid);

#pragma unroll
    for (int mt = 0; mt < 2; mt++) {
#pragma unroll
        for (int rr = 0; rr < 2; rr++) {
            const int m = m0 + wm * 32 + mt * 16 + g + rr * 8;
            float* dp = out + (size_t)m * D + n0 + wn * 64;
#pragma unroll
            for (int nt = 0; nt < 8; nt++) {
                const int col = nt * 8 + 2 * c;
                *(float2*)&dp[col] = make_float2(acc[mt][nt][rr * 2],
                                                 acc[mt][nt][rr * 2 + 1]);
            }
        }
    }
}

// ---------------------------------------------------------------------------
extern "C" void kernel_launch(void* const* d_in, const int* in_sizes, int n_in,
                              void* d_out, int out_size) {
    const float* x     = (const float*)d_in[0];
    const float* qkv_w = (const float*)d_in[1];
    const float* out_w = (const float*)d_in[2];

    cudaFuncSetAttribute(qkv_mm, cudaFuncAttributeMaxDynamicSharedMemorySize, GEMM_SMEM);
    cudaFuncSetAttribute(proj_mm, cudaFuncAttributeMaxDynamicSharedMemorySize, GEMM_SMEM);
    cudaFuncSetAttribute(attn_mma, cudaFuncAttributeMaxDynamicSharedMemorySize, ATTN_SMEM);

    prep_kernel<<<(NQKV + D + BT) / 8, 256>>>(x, qkv_w, out_w);
    qkv_mm<<<dim3(NQKV / 128, BT / 128), 256, GEMM_SMEM>>>();
    attn_mma<<<dim3(T / 256, H, B), 512, ATTN_SMEM>>>();
    proj_mm<<<dim3(D / 128, BT / 128), 256, GEMM_SMEM>>>((float*)d_out);
}